// round 3
// baseline (speedup 1.0000x reference)
#include <cuda_runtime.h>
#include <math.h>

#define BATCH 8192
#define NORB  128
#define NFER  32
#define HID   512
#define NOS   256          // orbital-sectors: 2 spin sectors * 128 orbitals

// ---------------- scratch (static device globals; no runtime allocation) ----
__device__ float    g_h[BATCH * HID];            // 16 MB  hidden activations
__device__ unsigned g_mask[BATCH * 8];           // 256-bit occupancy bitmask per sample
__device__ int      g_cnt[NOS];                  // bucket counts
__device__ int      g_list[NOS * BATCH];         // 8 MB   bucket entries: (b<<5)|slot
__device__ float    g_A[2 * BATCH * NFER * NFER];// 64 MB  gathered backflow matrices

// ---------------- K0: zero bucket counters (must rerun every replay) --------
__global__ void k_zero() {
    if (threadIdx.x < NOS) g_cnt[threadIdx.x] = 0;
}

// ---------------- K1: occupancy scan, bitmasks, bucket build ----------------
// one warp per sample; ballot gives ascending occupied order -> slot index
__global__ void k_index(const int* __restrict__ n) {
    int gw   = (blockIdx.x * blockDim.x + threadIdx.x) >> 5;
    int lane = threadIdx.x & 31;
    int b    = gw;                       // grid sized exactly: 8192 warps
    int cnt  = 0;
    #pragma unroll
    for (int c = 0; c < 8; c++) {
        if (c == 4) cnt = 0;             // sector boundary (k = 128)
        int v = n[b * 256 + c * 32 + lane];
        unsigned msk = __ballot_sync(0xffffffffu, v != 0);
        if (lane == 0) g_mask[b * 8 + c] = msk;
        int slot = cnt + __popc(msk & ((1u << lane) - 1u));
        cnt += __popc(msk);
        if (v) {
            int os  = ((c >> 2) << 7) | ((c & 3) << 5) | lane; // sector*128 + orbital
            int pos = atomicAdd(&g_cnt[os], 1);
            g_list[os * BATCH + pos] = (b << 5) | slot;
        }
    }
}

// ---------------- K2: h = tanh(b1 + sum of occupied W1 rows) ----------------
// warp per sample (occupancy loop is warp-uniform -> no divergence waste);
// 16 samples per CTA share each W1 smem tile.
__global__ void __launch_bounds__(512) k_hidden(const float* __restrict__ W1,
                                                const float* __restrict__ b1) {
    __shared__ __align__(16) float tile[16 * 512];   // 16 K-rows of W1, 32 KB
    int tid  = threadIdx.x;
    int lane = tid & 31;
    int wsam = tid >> 5;                 // 0..15
    int b    = blockIdx.x * 16 + wsam;

    float4 acc[4];
    #pragma unroll
    for (int i = 0; i < 4; i++) acc[i] = ((const float4*)b1)[i * 32 + lane];

    for (int t = 0; t < 16; t++) {
        int k0 = t * 16;
        __syncthreads();
        #pragma unroll
        for (int q = 0; q < 4; q++) {
            int ig = q * 512 + tid;      // 2048 float4 per tile
            ((float4*)tile)[ig] = ((const float4*)W1)[k0 * 128 + ig];
        }
        __syncthreads();
        unsigned bits = (g_mask[b * 8 + (t >> 1)] >> ((t & 1) * 16)) & 0xFFFFu;
        while (bits) {                   // warp-uniform loop
            int kk = __ffs(bits) - 1; bits &= bits - 1;
            const float4* row = (const float4*)(tile + kk * 512);
            #pragma unroll
            for (int i = 0; i < 4; i++) {
                float4 v = row[i * 32 + lane];   // conflict-free, interleaved chunks
                acc[i].x += v.x; acc[i].y += v.y; acc[i].z += v.z; acc[i].w += v.w;
            }
        }
    }
    float4* ho = (float4*)(g_h + b * HID);
    #pragma unroll
    for (int i = 0; i < 4; i++) {
        float4 v = acc[i];
        v.x = tanhf(v.x); v.y = tanhf(v.y); v.z = tanhf(v.z); v.w = tanhf(v.w);
        ho[i * 32 + lane] = v;
    }
}

// ---------------- K3: grouped masked GEMM -----------------------------------
// bucket os: (cnt x 512) @ (512 x 32) -> scatter A[b][slot][:] (+ M row + b2)
__global__ void __launch_bounds__(256) k_gemm(const float* __restrict__ W2,
                                              const float* __restrict__ b2,
                                              const float* __restrict__ M1,
                                              const float* __restrict__ M2) {
    __shared__ __align__(16) float ht[32 * 128];   // h tile, k-major: ht[kk][m]  16 KB
    __shared__ __align__(16) float wt[32 * 32];    // W2 tile: wt[kk][n]           4 KB
    __shared__ int   ents[128];

    int os = blockIdx.x;
    int mo = blockIdx.y << 7;
    int cnt = g_cnt[os];
    if (mo >= cnt) return;
    int mtile = min(128, cnt - mo);

    int tid = threadIdx.x;
    if (tid < 128) ents[tid] = g_list[os * BATCH + mo + min(tid, mtile - 1)];
    __syncthreads();

    int m = tid & 127;
    int q = tid >> 7;
    int bm = ents[m] >> 5;
    const float* hrow = g_h + (size_t)bm * HID;
    int nbase = os * 32;                 // == sector*4096 + orbital*32

    float acc[4][4];
    #pragma unroll
    for (int i = 0; i < 4; i++)
        #pragma unroll
        for (int j = 0; j < 4; j++) acc[i][j] = 0.0f;

    int tm = tid >> 3, tn = tid & 7;     // 32 x 8 thread grid, 4x4 microtile

    for (int kt = 0; kt < 16; kt++) {
        int k0 = kt * 32;
        __syncthreads();
        #pragma unroll
        for (int i = 0; i < 4; i++) {    // gather h rows (64B contiguous / thread)
            float4 v = *(const float4*)(hrow + k0 + q * 16 + i * 4);
            int kk = q * 16 + i * 4;
            ht[(kk + 0) * 128 + m] = v.x;
            ht[(kk + 1) * 128 + m] = v.y;
            ht[(kk + 2) * 128 + m] = v.z;
            ht[(kk + 3) * 128 + m] = v.w;
        }
        {
            float4 wv = *(const float4*)(W2 + (size_t)(k0 + (tid >> 3)) * 8192
                                            + nbase + (tid & 7) * 4);
            *(float4*)(wt + (tid >> 3) * 32 + (tid & 7) * 4) = wv;
        }
        __syncthreads();
        #pragma unroll
        for (int kk = 0; kk < 32; kk++) {
            float4 hv = *(const float4*)(ht + kk * 128 + (tm << 2));
            float4 wv = *(const float4*)(wt + (kk << 5) + (tn << 2));
            float hh[4] = {hv.x, hv.y, hv.z, hv.w};
            float ww[4] = {wv.x, wv.y, wv.z, wv.w};
            #pragma unroll
            for (int i = 0; i < 4; i++)
                #pragma unroll
                for (int j = 0; j < 4; j++)
                    acc[i][j] = fmaf(hh[i], ww[j], acc[i][j]);
        }
    }

    int s = os >> 7, o = os & 127;
    const float* M = s ? M2 : M1;
    float4 madd;
    madd.x = M[o * 32 + tn * 4 + 0] + b2[nbase + tn * 4 + 0];
    madd.y = M[o * 32 + tn * 4 + 1] + b2[nbase + tn * 4 + 1];
    madd.z = M[o * 32 + tn * 4 + 2] + b2[nbase + tn * 4 + 2];
    madd.w = M[o * 32 + tn * 4 + 3] + b2[nbase + tn * 4 + 3];

    #pragma unroll
    for (int i = 0; i < 4; i++) {
        int mm = (tm << 2) + i;
        if (mm < mtile) {
            int ent = ents[mm];
            int bb = ent >> 5, slot = ent & 31;
            float4 ov;
            ov.x = acc[i][0] + madd.x;
            ov.y = acc[i][1] + madd.y;
            ov.z = acc[i][2] + madd.z;
            ov.w = acc[i][3] + madd.w;
            *(float4*)(g_A + ((size_t)(s * BATCH + bb) * 32 + slot) * 32 + tn * 4) = ov;
        }
    }
}

// ---------------- K4: logdet via warp LU (smem, partial pivoting) -----------
// one warp per sample pair; matrix in smem [32][33] (conflict-free).
// Output: real part only (sum of log|det|) when wide==0;
// interleaved (real, pi*nneg) pairs when wide==1.
__global__ void __launch_bounds__(256) k_det(float* __restrict__ out, int wide) {
    __shared__ float As[8][32][33];
    int w    = threadIdx.x >> 5;
    int lane = threadIdx.x & 31;
    int b    = blockIdx.x * 8 + w;

    float la = 0.0f;
    int nneg = 0;

    for (int s = 0; s < 2; s++) {
        float (*A)[33] = As[w];
        const float* src = g_A + (((size_t)(s * BATCH + b)) << 10);
        #pragma unroll
        for (int r = 0; r < 32; r++) A[r][lane] = src[r * 32 + lane];
        __syncwarp();

        int neg = 0;
        for (int k = 0; k < 32; k++) {
            // partial pivot: argmax |A[r][k]| over rows r >= k (first-max tiebreak)
            float v = (lane >= k) ? fabsf(A[lane][k]) : -1.0f;
            int idx = lane;
            #pragma unroll
            for (int off = 16; off > 0; off >>= 1) {
                float ov = __shfl_xor_sync(0xffffffffu, v,   off);
                int   oi = __shfl_xor_sync(0xffffffffu, idx, off);
                if (ov > v || (ov == v && oi < idx)) { v = ov; idx = oi; }
            }
            int p = idx;                 // warp-uniform
            if (p != k) {                // swap rows k<->p (lane = column)
                float t = A[k][lane];
                A[k][lane] = A[p][lane];
                A[p][lane] = t;
                neg ^= 1;
            }
            __syncwarp();

            float piv = A[k][k];         // broadcast smem read
            neg ^= (piv < 0.0f) ? 1 : 0;
            la += logf(fabsf(piv));
            float inv = 1.0f / piv;
            float prow = A[k][lane];     // pivot row value at this column
            float mcol = A[lane][k];     // multiplier column (lane = row view)
            __syncwarp();
            for (int r = k + 1; r < 32; r++) {
                float mult = __shfl_sync(0xffffffffu, mcol, r) * inv;
                A[r][lane] = fmaf(-mult, prow, A[r][lane]);
            }
            __syncwarp();
        }
        nneg += neg;
    }
    if (lane == 0) {
        if (wide) {
            out[2 * b]     = la;
            out[2 * b + 1] = 3.14159274f * (float)nneg;
        } else {
            out[b] = la;                 // float32 output: real part of logdet sum
        }
    }
}

// ---------------- launch -----------------------------------------------------
// Inputs resolved by element count (robust to metadata ordering):
//   n  : 8192*256 = 2097152 (int32)     W1 : 256*512 = 131072
//   b1 : 512                            W2 : 512*8192 = 4194304
//   b2 : 8192                           M1, M2 : 128*32 = 4096 (kept in order)
extern "C" void kernel_launch(void* const* d_in, const int* in_sizes, int n_in,
                              void* d_out, int out_size) {
    const int*   n  = 0;
    const float *W1 = 0, *b1 = 0, *W2 = 0, *b2 = 0, *M1 = 0, *M2 = 0;
    for (int i = 0; i < n_in; i++) {
        switch (in_sizes[i]) {
            case 2097152: n  = (const int*)  d_in[i]; break;
            case 131072:  W1 = (const float*)d_in[i]; break;
            case 512:     b1 = (const float*)d_in[i]; break;
            case 4194304: W2 = (const float*)d_in[i]; break;
            case 8192:    b2 = (const float*)d_in[i]; break;
            case 4096:    if (!M1) M1 = (const float*)d_in[i];
                          else     M2 = (const float*)d_in[i];
                          break;
            default: break;
        }
    }

    int wide = (out_size >= 16384) ? 1 : 0;   // hedge: complex-pair layout if large

    k_zero  <<<1, 256>>>();
    k_index <<<BATCH / 8, 256>>>(n);
    k_hidden<<<BATCH / 16, 512>>>(W1, b1);
    k_gemm  <<<dim3(NOS, 64), 256>>>(W2, b2, M1, M2);
    k_det   <<<BATCH / 8, 256>>>((float*)d_out, wide);
}

// round 5
// speedup vs baseline: 1.2966x; 1.2966x over previous
#include <cuda_runtime.h>
#include <math.h>

#define BATCH 8192
#define NORB  128
#define NFER  32
#define HID   512
#define NOS   256          // orbital-sectors: 2 spin sectors * 128 orbitals

// ---------------- scratch (static device globals; no runtime allocation) ----
__device__ float    g_h[BATCH * HID];            // 16 MB  hidden activations (tf32-rounded)
__device__ unsigned g_mask[BATCH * 8];           // 256-bit occupancy bitmask per sample
__device__ int      g_cnt[NOS];                  // bucket counts
__device__ int      g_list[NOS * BATCH];         // 8 MB   bucket entries: (b<<5)|slot
__device__ float    g_A[2 * BATCH * NFER * NFER];// 64 MB  gathered backflow matrices

__device__ __forceinline__ unsigned f2tf32(float f) {
    unsigned u;
    asm("cvt.rna.tf32.f32 %0, %1;" : "=r"(u) : "f"(f));
    return u;
}

__device__ __forceinline__ void mma_tf32(float c[4],
                                         unsigned a0, unsigned a1,
                                         unsigned a2, unsigned a3,
                                         unsigned b0, unsigned b1) {
    asm volatile(
        "mma.sync.aligned.m16n8k8.row.col.f32.tf32.tf32.f32 "
        "{%0,%1,%2,%3}, {%4,%5,%6,%7}, {%8,%9}, {%0,%1,%2,%3};"
        : "+f"(c[0]), "+f"(c[1]), "+f"(c[2]), "+f"(c[3])
        : "r"(a0), "r"(a1), "r"(a2), "r"(a3), "r"(b0), "r"(b1));
}

// ---------------- K0: zero bucket counters (must rerun every replay) --------
__global__ void k_zero() {
    if (threadIdx.x < NOS) g_cnt[threadIdx.x] = 0;
}

// ---------------- K1: occupancy scan, bitmasks, bucket build ----------------
__global__ void k_index(const int* __restrict__ n) {
    int gw   = (blockIdx.x * blockDim.x + threadIdx.x) >> 5;
    int lane = threadIdx.x & 31;
    int b    = gw;
    int cnt  = 0;
    #pragma unroll
    for (int c = 0; c < 8; c++) {
        if (c == 4) cnt = 0;             // sector boundary (k = 128)
        int v = n[b * 256 + c * 32 + lane];
        unsigned msk = __ballot_sync(0xffffffffu, v != 0);
        if (lane == 0) g_mask[b * 8 + c] = msk;
        int slot = cnt + __popc(msk & ((1u << lane) - 1u));
        cnt += __popc(msk);
        if (v) {
            int os  = ((c >> 2) << 7) | ((c & 3) << 5) | lane;
            int pos = atomicAdd(&g_cnt[os], 1);
            g_list[os * BATCH + pos] = (b << 5) | slot;
        }
    }
}

// ---------------- K2: h = tanh(b1 + sum of occupied W1 rows) ----------------
// output rounded to tf32 (g_h feeds only the tensor-core GEMM)
__global__ void __launch_bounds__(512) k_hidden(const float* __restrict__ W1,
                                                const float* __restrict__ b1) {
    __shared__ __align__(16) float tile[16 * 512];
    int tid  = threadIdx.x;
    int lane = tid & 31;
    int wsam = tid >> 5;
    int b    = blockIdx.x * 16 + wsam;

    float4 acc[4];
    #pragma unroll
    for (int i = 0; i < 4; i++) acc[i] = ((const float4*)b1)[i * 32 + lane];

    for (int t = 0; t < 16; t++) {
        int k0 = t * 16;
        __syncthreads();
        #pragma unroll
        for (int q = 0; q < 4; q++) {
            int ig = q * 512 + tid;
            ((float4*)tile)[ig] = ((const float4*)W1)[k0 * 128 + ig];
        }
        __syncthreads();
        unsigned bits = (g_mask[b * 8 + (t >> 1)] >> ((t & 1) * 16)) & 0xFFFFu;
        while (bits) {
            int kk = __ffs(bits) - 1; bits &= bits - 1;
            const float4* row = (const float4*)(tile + kk * 512);
            #pragma unroll
            for (int i = 0; i < 4; i++) {
                float4 v = row[i * 32 + lane];
                acc[i].x += v.x; acc[i].y += v.y; acc[i].z += v.z; acc[i].w += v.w;
            }
        }
    }
    float4* ho = (float4*)(g_h + b * HID);
    #pragma unroll
    for (int i = 0; i < 4; i++) {
        float4 v = acc[i];
        v.x = __uint_as_float(f2tf32(tanhf(v.x)));
        v.y = __uint_as_float(f2tf32(tanhf(v.y)));
        v.z = __uint_as_float(f2tf32(tanhf(v.z)));
        v.w = __uint_as_float(f2tf32(tanhf(v.w)));
        ho[i * 32 + lane] = v;
    }
}

// ---------------- K3: grouped masked GEMM (tf32 tensor cores) ---------------
// bucket os: (cnt x 512) @ (512 x 32) -> scatter A[b][slot][:] (+ M row + b2)
// 8 warps, each computes a 16m x 32n warp-tile via mma.m16n8k8.tf32.
// ht m-major [128][36] / wt n-major [32][36]: pad 36 makes every fragment
// load conflict-free (addr mod 32 = 4*(lane>>2)+(lane&3), all distinct).
__global__ void __launch_bounds__(256) k_gemm(const float* __restrict__ W2,
                                              const float* __restrict__ b2,
                                              const float* __restrict__ M1,
                                              const float* __restrict__ M2) {
    __shared__ __align__(16) float ht[128][36];
    __shared__ __align__(16) float wt[32][36];
    __shared__ int ents[128];

    int os = blockIdx.x;
    int mo = blockIdx.y << 7;
    int cnt = g_cnt[os];
    if (mo >= cnt) return;
    int mtile = min(128, cnt - mo);

    int tid = threadIdx.x;
    if (tid < 128) ents[tid] = g_list[os * BATCH + mo + min(tid, mtile - 1)];
    __syncthreads();

    int m = tid & 127;
    int q = tid >> 7;                    // two threads per h row
    const float* hrow = g_h + (size_t)(ents[m] >> 5) * HID;
    int nbase = os * 32;

    int w    = tid >> 5;                 // warp id, m0 = w*16
    int lane = tid & 31;
    int gr   = lane >> 2;                // group row 0..7
    int tg   = lane & 3;                 // thread-in-group 0..3
    int m0   = w << 4;

    float acc[4][4];
    #pragma unroll
    for (int nb = 0; nb < 4; nb++)
        #pragma unroll
        for (int i = 0; i < 4; i++) acc[nb][i] = 0.0f;

    for (int kt = 0; kt < 16; kt++) {
        int k0 = kt * 32;
        __syncthreads();
        // stage h tile (m-major): 8 float4 chunks per row, 2 threads/row
        #pragma unroll
        for (int i = 0; i < 4; i++) {
            int jc = q * 4 + i;          // chunk 0..7
            float4 v = *(const float4*)(hrow + k0 + jc * 4);
            *(float4*)(&ht[m][jc * 4]) = v;
        }
        // stage W2 tile transposed to n-major, tf32-rounded
        {
            int kk = tid >> 3, nq = tid & 7;
            float4 wv = *(const float4*)(W2 + (size_t)(k0 + kk) * 8192
                                            + nbase + nq * 4);
            wt[nq * 4 + 0][kk] = __uint_as_float(f2tf32(wv.x));
            wt[nq * 4 + 1][kk] = __uint_as_float(f2tf32(wv.y));
            wt[nq * 4 + 2][kk] = __uint_as_float(f2tf32(wv.z));
            wt[nq * 4 + 3][kk] = __uint_as_float(f2tf32(wv.w));
        }
        __syncthreads();

        #pragma unroll
        for (int ks = 0; ks < 4; ks++) {
            int kb = ks * 8;
            unsigned a0 = __float_as_uint(ht[m0 + gr    ][kb + tg    ]);
            unsigned a1 = __float_as_uint(ht[m0 + gr + 8][kb + tg    ]);
            unsigned a2 = __float_as_uint(ht[m0 + gr    ][kb + tg + 4]);
            unsigned a3 = __float_as_uint(ht[m0 + gr + 8][kb + tg + 4]);
            #pragma unroll
            for (int nb = 0; nb < 4; nb++) {
                unsigned b0 = __float_as_uint(wt[nb * 8 + gr][kb + tg    ]);
                unsigned b1 = __float_as_uint(wt[nb * 8 + gr][kb + tg + 4]);
                mma_tf32(acc[nb], a0, a1, a2, a3, b0, b1);
            }
        }
    }

    // epilogue: + M row + b2, scatter by (b, slot)
    int s = os >> 7, o = os & 127;
    const float* M = s ? M2 : M1;
    int mmA = m0 + gr;                   // c0,c1 row
    int mmB = m0 + gr + 8;               // c2,c3 row
    int entA = ents[mmA < mtile ? mmA : 0];
    int entB = ents[mmB < mtile ? mmB : 0];
    float* rowA = g_A + ((size_t)(s * BATCH + (entA >> 5)) * 32 + (entA & 31)) * 32;
    float* rowB = g_A + ((size_t)(s * BATCH + (entB >> 5)) * 32 + (entB & 31)) * 32;

    #pragma unroll
    for (int nb = 0; nb < 4; nb++) {
        int col = nb * 8 + 2 * tg;
        float mb0 = M[o * 32 + col]     + b2[nbase + col];
        float mb1 = M[o * 32 + col + 1] + b2[nbase + col + 1];
        if (mmA < mtile)
            *(float2*)(rowA + col) = make_float2(acc[nb][0] + mb0, acc[nb][1] + mb1);
        if (mmB < mtile)
            *(float2*)(rowB + col) = make_float2(acc[nb][2] + mb0, acc[nb][3] + mb1);
    }
}

// ---------------- K4: logdet via warp LU (smem, partial pivoting) -----------
__global__ void __launch_bounds__(256) k_det(float* __restrict__ out, int wide) {
    __shared__ float As[8][32][33];
    int w    = threadIdx.x >> 5;
    int lane = threadIdx.x & 31;
    int b    = blockIdx.x * 8 + w;

    float la = 0.0f;
    int nneg = 0;

    for (int s = 0; s < 2; s++) {
        float (*A)[33] = As[w];
        const float* src = g_A + (((size_t)(s * BATCH + b)) << 10);
        #pragma unroll
        for (int r = 0; r < 32; r++) A[r][lane] = src[r * 32 + lane];
        __syncwarp();

        int neg = 0;
        for (int k = 0; k < 32; k++) {
            float v = (lane >= k) ? fabsf(A[lane][k]) : -1.0f;
            int idx = lane;
            #pragma unroll
            for (int off = 16; off > 0; off >>= 1) {
                float ov = __shfl_xor_sync(0xffffffffu, v,   off);
                int   oi = __shfl_xor_sync(0xffffffffu, idx, off);
                if (ov > v || (ov == v && oi < idx)) { v = ov; idx = oi; }
            }
            int p = idx;
            if (p != k) {
                float t = A[k][lane];
                A[k][lane] = A[p][lane];
                A[p][lane] = t;
                neg ^= 1;
            }
            __syncwarp();

            float piv = A[k][k];
            neg ^= (piv < 0.0f) ? 1 : 0;
            la += logf(fabsf(piv));
            float inv = 1.0f / piv;
            float prow = A[k][lane];
            float mcol = A[lane][k];
            __syncwarp();
            for (int r = k + 1; r < 32; r++) {
                float mult = __shfl_sync(0xffffffffu, mcol, r) * inv;
                A[r][lane] = fmaf(-mult, prow, A[r][lane]);
            }
            __syncwarp();
        }
        nneg += neg;
    }
    if (lane == 0) {
        if (wide) {
            out[2 * b]     = la;
            out[2 * b + 1] = 3.14159274f * (float)nneg;
        } else {
            out[b] = la;
        }
    }
}

// ---------------- launch -----------------------------------------------------
extern "C" void kernel_launch(void* const* d_in, const int* in_sizes, int n_in,
                              void* d_out, int out_size) {
    const int*   n  = 0;
    const float *W1 = 0, *b1 = 0, *W2 = 0, *b2 = 0, *M1 = 0, *M2 = 0;
    for (int i = 0; i < n_in; i++) {
        switch (in_sizes[i]) {
            case 2097152: n  = (const int*)  d_in[i]; break;
            case 131072:  W1 = (const float*)d_in[i]; break;
            case 512:     b1 = (const float*)d_in[i]; break;
            case 4194304: W2 = (const float*)d_in[i]; break;
            case 8192:    b2 = (const float*)d_in[i]; break;
            case 4096:    if (!M1) M1 = (const float*)d_in[i];
                          else     M2 = (const float*)d_in[i];
                          break;
            default: break;
        }
    }

    int wide = (out_size >= 16384) ? 1 : 0;

    k_zero  <<<1, 256>>>();
    k_index <<<BATCH / 8, 256>>>(n);
    k_hidden<<<BATCH / 16, 512>>>(W1, b1);
    k_gemm  <<<dim3(NOS, 64), 256>>>(W2, b2, M1, M2);
    k_det   <<<BATCH / 8, 256>>>((float*)d_out, wide);
}